// round 14
// baseline (speedup 1.0000x reference)
#include <cuda_runtime.h>
#include <math.h>

#define SS 256
#define BB 32
#define EE 768
#define HH 512
#define CC 30
#define MTOT (SS*BB)      // 8192
#define G4 2048
#define K0P 776           // 770 padded to multiple of 8
#define K1 1024

// ---------------- scratch (device globals) ----------------------------------
__device__ float d_x0[(size_t)MTOT * K0P];          // layer0 input, padded, [s*32+b][776]
__device__ float d_meanword[MTOT];                  // [b][s]
__device__ float d_meanpred[BB];
__device__ float d_wpad[2][(size_t)G4 * K0P];       // padded Wih_l0 (f,b)
__device__ float d_G[2][(size_t)MTOT * G4];         // gate preactivations (xW+bias), per dir
__device__ float d_h[2][(size_t)SS * BB * HH];      // h per iter [dir][t][b][k]
__device__ float d_x1[(size_t)MTOT * K1];           // layer1 input [s*32+b][1024]
__device__ float d_x2[(size_t)MTOT * K1];           // layer2 output (final proj input)
__device__ volatile int d_flag[2][64];

__device__ __forceinline__ float sigmf(float x) { return 0.5f + 0.5f * tanhf(0.5f * x); }

__device__ __forceinline__ unsigned long long dup2(float a) {
    unsigned long long r;
    asm("mov.b64 %0, {%1, %1};" : "=l"(r) : "r"(__float_as_uint(a)));
    return r;
}
__device__ __forceinline__ void ffma2(unsigned long long& d, unsigned long long a,
                                      unsigned long long b) {
    asm("fma.rn.f32x2 %0, %1, %2, %0;" : "+l"(d) : "l"(a), "l"(b));
}

// ---------------- feature prep (proven R1) -----------------------------------
__global__ __launch_bounds__(256) void prep_mean(const float* __restrict__ hs) {
    int b = blockIdx.x >> 8;
    int s = blockIdx.x & 255;
    int tid = threadIdx.x;
    const size_t L = (size_t)BB * SS * EE;
    const float* p = hs + ((size_t)b * SS + s) * EE;
    float* xrow = d_x0 + ((size_t)s * BB + b) * K0P;
    float lsum = 0.f;
    for (int e = tid; e < EE; e += 256) {
        float v = 0.25f * (p[e] + p[e + L] + p[e + 2 * L] + p[e + 3 * L]);
        xrow[e] = v;
        lsum += v;
    }
    __shared__ float red[256];
    red[tid] = lsum;
    __syncthreads();
    for (int o = 128; o > 0; o >>= 1) {
        if (tid < o) red[tid] += red[tid + o];
        __syncthreads();
    }
    if (tid == 0) d_meanword[b * SS + s] = red[0] * (1.0f / 768.0f);
    if (tid < 6) xrow[770 + tid] = 0.f;  // zero pad cols
}

__global__ void predk(const int* __restrict__ pred) {
    int b = threadIdx.x;  // 32 threads
    const int* p = pred + b * SS;
    int best = p[0], idx = 0;
    for (int s = 1; s < SS; s++) {
        if (p[s] > best) { best = p[s]; idx = s; }
    }
    d_meanpred[b] = d_meanword[b * SS + idx];
}

__global__ __launch_bounds__(256) void finishx(const int* __restrict__ roles) {
    int i = blockIdx.x * 256 + threadIdx.x;  // 8192 = b*256+s
    int b = i >> 8, s = i & 255;
    float* xrow = d_x0 + ((size_t)s * BB + b) * K0P;
    xrow[EE] = d_meanword[i] - d_meanpred[b];
    int r = roles[i];
    xrow[EE + 1] = (r != 0 && r != -100) ? 1.f : 0.f;
}

__global__ __launch_bounds__(256) void wpadk(const float* __restrict__ w0,
                                             const float* __restrict__ w1) {
    size_t i = (size_t)blockIdx.x * 256 + threadIdx.x;
    const size_t per = (size_t)G4 * K0P;
    if (i >= 2 * per) return;
    int dir = (int)(i / per);
    size_t r = i % per;
    int row = (int)(r / K0P), col = (int)(r % K0P);
    const float* w = dir ? w1 : w0;
    d_wpad[dir][r] = (col < 770) ? w[(size_t)row * 770 + col] : 0.f;
}

// ---------------- input-projection GEMM (proven R1) --------------------------
__global__ __launch_bounds__(256) void sgemm_bias(const float* __restrict__ Wext,
                                                  const float* __restrict__ b1,
                                                  const float* __restrict__ b2,
                                                  int dir, int layer) {
    const int K = layer ? K1 : K0P;
    const float* A = layer ? d_x1 : d_x0;
    const float* W = layer ? Wext : d_wpad[dir];
    float* C = d_G[dir];

    __shared__ float Asm[8][128];
    __shared__ float Bsm[8][128];
    int tid = threadIdx.x;
    int m0 = blockIdx.y * 128, n0 = blockIdx.x * 128;
    int lr = tid >> 1, lc = (tid & 1) * 4;
    int tx = tid & 15, ty = tid >> 4;

    float acc[8][8];
#pragma unroll
    for (int i = 0; i < 8; i++)
#pragma unroll
        for (int j = 0; j < 8; j++) acc[i][j] = 0.f;

    const float* Ap = A + (size_t)(m0 + lr) * K + lc;
    const float* Wp = W + (size_t)(n0 + lr) * K + lc;

    for (int k0 = 0; k0 < K; k0 += 8) {
        float4 av = *(const float4*)(Ap + k0);
        float4 wv = *(const float4*)(Wp + k0);
        __syncthreads();
        Asm[lc + 0][lr] = av.x; Asm[lc + 1][lr] = av.y;
        Asm[lc + 2][lr] = av.z; Asm[lc + 3][lr] = av.w;
        Bsm[lc + 0][lr] = wv.x; Bsm[lc + 1][lr] = wv.y;
        Bsm[lc + 2][lr] = wv.z; Bsm[lc + 3][lr] = wv.w;
        __syncthreads();
#pragma unroll
        for (int kk = 0; kk < 8; kk++) {
            float4 a0 = *(const float4*)&Asm[kk][ty * 8];
            float4 a1 = *(const float4*)&Asm[kk][ty * 8 + 4];
            float4 c0 = *(const float4*)&Bsm[kk][tx * 8];
            float4 c1 = *(const float4*)&Bsm[kk][tx * 8 + 4];
            float aa[8] = {a0.x, a0.y, a0.z, a0.w, a1.x, a1.y, a1.z, a1.w};
            float bb[8] = {c0.x, c0.y, c0.z, c0.w, c1.x, c1.y, c1.z, c1.w};
#pragma unroll
            for (int i = 0; i < 8; i++)
#pragma unroll
                for (int j = 0; j < 8; j++) acc[i][j] = fmaf(aa[i], bb[j], acc[i][j]);
        }
    }
    float bs[8];
#pragma unroll
    for (int j = 0; j < 8; j++) bs[j] = b1[n0 + tx * 8 + j] + b2[n0 + tx * 8 + j];
#pragma unroll
    for (int i = 0; i < 8; i++)
#pragma unroll
        for (int j = 0; j < 8; j++)
            C[(size_t)(m0 + ty * 8 + i) * G4 + n0 + tx * 8 + j] = acc[i][j] + bs[j];
}

// ---------------- persistent recurrence (exonerated by bitwise chain) --------
__global__ void resetflags(void) {
    int i = threadIdx.x;
    if (i < 128) d_flag[i >> 6][i & 63] = 0;
}

// 128 blocks x 256 threads. Block: dir = bid>>6, j0 = (bid&63)*8.
// Thread: tx = j offset (0..7), ty = batch (0..31). c-state in registers.
// smem: Ws[512][32] (64KB) + Hs[32][520] (66.5KB).
template <int LAYER>
__global__ __launch_bounds__(256) void lstm_persist(const float* __restrict__ WhhF,
                                                    const float* __restrict__ WhhB) {
    extern __shared__ float sm[];
    float* Ws = sm;               // [k][jg], jg = jj*4 + gate
    float* Hs = sm + 512 * 32;    // [b][k], row stride 520

    int bid = blockIdx.x;
    int dir = bid >> 6, jb = bid & 63, j0 = jb * 8;
    const float* Whh = dir ? WhhB : WhhF;
    int tid = threadIdx.x;
    int tx = tid & 7, ty = tid >> 3;

    // stage Whh slice: thread (jg = tid&31, kg = tid>>5) loads 64 k values
    {
        int jg = tid & 31, kg = tid >> 5;
        int gate = jg & 3, jj = jg >> 2;
        const float* wrow = Whh + (size_t)(gate * HH + j0 + jj) * HH + kg * 64;
#pragma unroll
        for (int q = 0; q < 16; q++) {
            float4 v = *(const float4*)(wrow + q * 4);
            int k = kg * 64 + q * 4;
            Ws[(k + 0) * 32 + jg] = v.x;
            Ws[(k + 1) * 32 + jg] = v.y;
            Ws[(k + 2) * 32 + jg] = v.z;
            Ws[(k + 3) * 32 + jg] = v.w;
        }
    }
    __syncthreads();

    const float* Gd = d_G[dir];
    float* hbase = d_h[dir];
    const float* hrow = Hs + ty * 520;
    float c = 0.f;

    for (int t = 0; t < SS; t++) {
        int s = dir ? (SS - 1 - t) : t;
        // prefetch gate preacts (independent of h)
        const float* Gp = Gd + ((size_t)s * BB + ty) * G4 + j0 + tx;
        float g0 = Gp[0], g1 = Gp[HH], g2 = Gp[2 * HH], g3 = Gp[3 * HH];

        unsigned long long acc_if = 0ull, acc_go = 0ull;
        if (t > 0) {
            // stage h(t-1) into Hs [b][k]
            const float4* src = (const float4*)(hbase + (size_t)(t - 1) * (BB * HH));
#pragma unroll
            for (int r = 0; r < 16; r++) {
                int ci = tid + r * 256;
                float4 v = src[ci];
                int flat = ci * 4, b = flat >> 9, k = flat & 511;
                *(float4*)&Hs[b * 520 + k] = v;
            }
            __syncthreads();

#pragma unroll 4
            for (int k0 = 0; k0 < HH; k0 += 4) {
                float4 a4 = *(const float4*)(hrow + k0);
                const float* wb = Ws + k0 * 32 + tx * 4;
#define LKK(AV, OFF)                                                  \
    {                                                                 \
        unsigned long long aa = dup2(AV);                             \
        double2 wd = *(const double2*)(wb + (OFF));                   \
        ffma2(acc_if, aa, __double_as_longlong(wd.x));                \
        ffma2(acc_go, aa, __double_as_longlong(wd.y));                \
    }
                LKK(a4.x, 0)
                LKK(a4.y, 32)
                LKK(a4.z, 64)
                LKK(a4.w, 96)
#undef LKK
            }
        }

        float gi = __uint_as_float((unsigned)acc_if) + g0;
        float gf = __uint_as_float((unsigned)(acc_if >> 32)) + g1;
        float gg = __uint_as_float((unsigned)acc_go) + g2;
        float go = __uint_as_float((unsigned)(acc_go >> 32)) + g3;
        float cn = sigmf(gf) * c + sigmf(gi) * tanhf(gg);
        float hh = sigmf(go) * tanhf(cn);
        c = cn;

        hbase[(size_t)t * (BB * HH) + ty * HH + j0 + tx] = hh;
        size_t xi = ((size_t)s * BB + ty) * K1 + dir * HH + j0 + tx;
        if (LAYER == 0) d_x1[xi] = hh;
        else            d_x2[xi] = hh;

        // grid barrier (per direction, 64 blocks); BOUNDED spin.
        __threadfence();
        __syncthreads();
        if (tid == 0) d_flag[dir][jb] = t + 1;
        if (t < SS - 1) {
            for (int it = 0; it < (1 << 16); it++) {
                int ok = 1;
                if (tid < 64) ok = (d_flag[dir][tid] >= t + 1);
                if (__syncthreads_and(ok)) break;
            }
            __threadfence();
        }
    }
}

// ---------------- final projection (proven R1) -------------------------------
__global__ __launch_bounds__(256) void outk(const float* __restrict__ Wout,
                                            const float* __restrict__ bout,
                                            float* __restrict__ out) {
    int bi = blockIdx.x;  // b*256+s
    int b = bi >> 8, s = bi & 255;
    const float* xr = d_x2 + ((size_t)s * BB + b) * K1;
    __shared__ float xs[K1];
    int tid = threadIdx.x;
    ((float4*)xs)[tid] = ((const float4*)xr)[tid];
    __syncthreads();
    int g = tid >> 3, lane = tid & 7;
    int gc = (g < CC) ? g : (CC - 1);
    const float* w = Wout + (size_t)gc * K1;
    float sum = 0.f;
    for (int k = lane; k < K1; k += 8) sum = fmaf(xs[k], w[k], sum);
    sum += __shfl_down_sync(0xffffffffu, sum, 4, 8);
    sum += __shfl_down_sync(0xffffffffu, sum, 2, 8);
    sum += __shfl_down_sync(0xffffffffu, sum, 1, 8);
    if (lane == 0 && g < CC)
        out[((size_t)b * SS + s) * CC + g] = sum + bout[g];
}

// ---------------- launch -----------------------------------------------------
extern "C" void kernel_launch(void* const* d_in, const int* in_sizes, int n_in,
                              void* d_out, int out_size) {
    const float* hs    = (const float*)d_in[0];
    const int*   roles = (const int*)d_in[1];
    const int*   preds = (const int*)d_in[2];
    const float* Wih0f = (const float*)d_in[3];
    const float* Whh0f = (const float*)d_in[4];
    const float* bih0f = (const float*)d_in[5];
    const float* bhh0f = (const float*)d_in[6];
    const float* Wih0b = (const float*)d_in[7];
    const float* Whh0b = (const float*)d_in[8];
    const float* bih0b = (const float*)d_in[9];
    const float* bhh0b = (const float*)d_in[10];
    const float* Wih1f = (const float*)d_in[11];
    const float* Whh1f = (const float*)d_in[12];
    const float* bih1f = (const float*)d_in[13];
    const float* bhh1f = (const float*)d_in[14];
    const float* Wih1b = (const float*)d_in[15];
    const float* Whh1b = (const float*)d_in[16];
    const float* bih1b = (const float*)d_in[17];
    const float* bhh1b = (const float*)d_in[18];
    const float* Wout  = (const float*)d_in[19];
    const float* bout  = (const float*)d_in[20];
    float* out = (float*)d_out;

    const int LSTM_SMEM = (512 * 32 + 32 * 520) * 4;  // 132096 B
    cudaFuncSetAttribute(lstm_persist<0>, cudaFuncAttributeMaxDynamicSharedMemorySize, LSTM_SMEM);
    cudaFuncSetAttribute(lstm_persist<1>, cudaFuncAttributeMaxDynamicSharedMemorySize, LSTM_SMEM);

    // feature prep
    prep_mean<<<MTOT, 256>>>(hs);
    predk<<<1, 32>>>(preds);
    finishx<<<32, 256>>>(roles);
    wpadk<<<12416, 256>>>(Wih0f, Wih0b);

    dim3 gg(G4 / 128, MTOT / 128);  // (16, 64)

    // layer 0
    sgemm_bias<<<gg, 256>>>(nullptr, bih0f, bhh0f, 0, 0);
    sgemm_bias<<<gg, 256>>>(nullptr, bih0b, bhh0b, 1, 0);
    resetflags<<<1, 128>>>();
    lstm_persist<0><<<128, 256, LSTM_SMEM>>>(Whh0f, Whh0b);

    // layer 1
    sgemm_bias<<<gg, 256>>>(Wih1f, bih1f, bhh1f, 0, 1);
    sgemm_bias<<<gg, 256>>>(Wih1b, bih1b, bhh1b, 1, 1);
    resetflags<<<1, 128>>>();
    lstm_persist<1><<<128, 256, LSTM_SMEM>>>(Whh1f, Whh1b);

    // output projection
    outk<<<MTOT, 256>>>(Wout, bout, out);
}